// round 5
// baseline (speedup 1.0000x reference)
#include <cuda_runtime.h>
#include <cuda_bf16.h>
#include <cstdint>

// Problem constants (fixed shapes for this problem)
#define NN 100000
#define NE 1600000

// ---------------- scratch (device globals; referenced ONLY from device code)
__device__ float g_H[(size_t)NN * 128];    // GEMM output / agg input
__device__ float g_G[(size_t)NN * 128];    // agg output / next GEMM input
__device__ int   g_deg[NN];
__device__ int   g_rowptr[NN + 1];
__device__ int   g_cursor[NN];
__device__ int   g_col[NE];
__device__ float g_dinv[NN];
__device__ int   g_scantmp[NN];
__device__ int   g_bsums[128];

// ---------------- f32x2 packed-FMA helpers (sm_103a) ------------------------
__device__ __forceinline__ unsigned long long pack2(float lo, float hi) {
    unsigned long long r;
    asm("mov.b64 %0, {%1, %2};" : "=l"(r) : "f"(lo), "f"(hi));
    return r;
}
__device__ __forceinline__ void ffma2(unsigned long long& d,
                                      unsigned long long a,
                                      unsigned long long b) {
    asm("fma.rn.f32x2 %0, %1, %2, %0;" : "+l"(d) : "l"(a), "l"(b));
}
__device__ __forceinline__ void unpack2(float& lo, float& hi, unsigned long long v) {
    asm("mov.b64 {%0, %1}, %2;" : "=f"(lo), "=f"(hi) : "l"(v));
}

// ---------------- graph prep -----------------------------------------------
__global__ void k_zero_deg(int n) {
    int i = blockIdx.x * blockDim.x + threadIdx.x;
    if (i < n) g_deg[i] = 0;
}

__global__ void k_count(const int* __restrict__ dst, int e) {
    int i = blockIdx.x * blockDim.x + threadIdx.x;
    if (i < e) atomicAdd(&g_deg[dst[i]], 1);
}

__global__ void k_scan_block(int n) {
    int tid = threadIdx.x, lane = tid & 31, wid = tid >> 5;
    int i = blockIdx.x * 1024 + tid;
    int v = (i < n) ? g_deg[i] : 0;
    #pragma unroll
    for (int o = 1; o < 32; o <<= 1) {
        int t = __shfl_up_sync(0xffffffffu, v, o);
        if (lane >= o) v += t;
    }
    __shared__ int ws[32];
    if (lane == 31) ws[wid] = v;
    __syncthreads();
    if (wid == 0) {
        int w = ws[lane];
        #pragma unroll
        for (int o = 1; o < 32; o <<= 1) {
            int t = __shfl_up_sync(0xffffffffu, w, o);
            if (lane >= o) w += t;
        }
        ws[lane] = w;
    }
    __syncthreads();
    if (wid > 0) v += ws[wid - 1];
    if (i < n) g_scantmp[i] = v;
    if (tid == 1023) g_bsums[blockIdx.x] = v;
}

__global__ void k_scan_sums(int nb) {
    if (threadIdx.x == 0 && blockIdx.x == 0) {
        int acc = 0;
        for (int b = 0; b < nb; b++) {
            int t = g_bsums[b];
            g_bsums[b] = acc;
            acc += t;
        }
    }
}

__global__ void k_finalize(int n) {
    int i = blockIdx.x * 1024 + threadIdx.x;
    if (i >= n) return;
    int incl = g_scantmp[i] + g_bsums[blockIdx.x];
    int d = g_deg[i];
    int excl = incl - d;
    g_cursor[i] = excl;
    g_rowptr[i] = excl;
    if (i == n - 1) g_rowptr[n] = incl;
    g_dinv[i] = rsqrtf((float)(d + 1));  // +1: self-loop
}

__global__ void k_scatter(const int* __restrict__ src,
                          const int* __restrict__ dst, int e) {
    int i = blockIdx.x * blockDim.x + threadIdx.x;
    if (i < e) {
        int d = dst[i];
        int p = atomicAdd(&g_cursor[d], 1);
        g_col[p] = src[i];
    }
}

// ---------------- fast GEMM (f32x2): C[M,128] = A[M,128] @ W[128,128] ------
// BM=128, BN=128, BK=16, 256 threads, 8x8 outputs/thread via packed FFMA2.
// A_SEL: 0 = param x, 1 = g_G.  C = g_H.
template <int A_SEL>
__global__ void __launch_bounds__(256, 2)
gemm128_f2_k(const float* __restrict__ Ap, const float* __restrict__ W, int M) {
    const float* __restrict__ A = (A_SEL == 0) ? Ap : (const float*)g_G;
    float* __restrict__ C = (float*)g_H;
    constexpr int BM = 128, BN = 128, BK = 16, K = 128;

    __shared__ float As[BK][BM];   // k-major (transposed on store)
    __shared__ float Ws[BK][BN];

    const int tid = threadIdx.x;
    const int tx = tid & 15;           // 0..15, col group (8 cols)
    const int ty = tid >> 4;           // 0..15, row group (8 rows)
    const int rowBase = blockIdx.x * BM;

    // A-load mapping: thread handles one row, half the k's
    const int ar   = tid & 127;        // row within tile
    const int ak0  = (tid >> 7) * 8;   // k offset 0 or 8
    // W-load mapping: thread handles one k-row, 8 cols
    const int wk   = tid >> 4;         // 0..15
    const int wc0  = (tid & 15) * 8;   // col offset

    unsigned long long acc[8][4];
    #pragma unroll
    for (int i = 0; i < 8; i++)
        #pragma unroll
        for (int j = 0; j < 4; j++) acc[i][j] = 0ull;

    for (int kt = 0; kt < K; kt += BK) {
        // Load A tile [BM x BK] and store transposed into As[k][row]
        {
            const int gr = rowBase + ar;
            float4 v0, v1;
            if (gr < M) {
                v0 = *(const float4*)&A[(size_t)gr * K + kt + ak0];
                v1 = *(const float4*)&A[(size_t)gr * K + kt + ak0 + 4];
            } else {
                v0 = make_float4(0.f, 0.f, 0.f, 0.f);
                v1 = v0;
            }
            As[ak0 + 0][ar] = v0.x; As[ak0 + 1][ar] = v0.y;
            As[ak0 + 2][ar] = v0.z; As[ak0 + 3][ar] = v0.w;
            As[ak0 + 4][ar] = v1.x; As[ak0 + 5][ar] = v1.y;
            As[ak0 + 6][ar] = v1.z; As[ak0 + 7][ar] = v1.w;
        }
        // Load W tile [BK x BN]
        {
            const float4 w0 = *(const float4*)&W[(size_t)(kt + wk) * 128 + wc0];
            const float4 w1 = *(const float4*)&W[(size_t)(kt + wk) * 128 + wc0 + 4];
            *(float4*)&Ws[wk][wc0] = w0;
            *(float4*)&Ws[wk][wc0 + 4] = w1;
        }
        __syncthreads();

        #pragma unroll
        for (int kk = 0; kk < BK; kk++) {
            float4 a0 = *(const float4*)&As[kk][ty * 8];
            float4 a1 = *(const float4*)&As[kk][ty * 8 + 4];
            float4 b0 = *(const float4*)&Ws[kk][tx * 8];
            float4 b1 = *(const float4*)&Ws[kk][tx * 8 + 4];
            unsigned long long bp0 = pack2(b0.x, b0.y);
            unsigned long long bp1 = pack2(b0.z, b0.w);
            unsigned long long bp2 = pack2(b1.x, b1.y);
            unsigned long long bp3 = pack2(b1.z, b1.w);
            float av[8] = {a0.x, a0.y, a0.z, a0.w, a1.x, a1.y, a1.z, a1.w};
            #pragma unroll
            for (int i = 0; i < 8; i++) {
                unsigned long long ai = pack2(av[i], av[i]);
                ffma2(acc[i][0], ai, bp0);
                ffma2(acc[i][1], ai, bp1);
                ffma2(acc[i][2], ai, bp2);
                ffma2(acc[i][3], ai, bp3);
            }
        }
        __syncthreads();
    }

    #pragma unroll
    for (int i = 0; i < 8; i++) {
        const int gr = rowBase + ty * 8 + i;
        if (gr >= M) continue;
        float o[8];
        unpack2(o[0], o[1], acc[i][0]);
        unpack2(o[2], o[3], acc[i][1]);
        unpack2(o[4], o[5], acc[i][2]);
        unpack2(o[6], o[7], acc[i][3]);
        *(float4*)&C[(size_t)gr * 128 + tx * 8]     = make_float4(o[0], o[1], o[2], o[3]);
        *(float4*)&C[(size_t)gr * 128 + tx * 8 + 4] = make_float4(o[4], o[5], o[6], o[7]);
    }
}

// ---------------- small GEMM for layer 3: C[M,40] = A[M,128] @ W[128,40] ----
__global__ void gemm40_k(const float* __restrict__ W, int M) {
    const float* __restrict__ A = (const float*)g_G;
    float* __restrict__ C = (float*)g_H;
    constexpr int BM = 64, BK = 32, K = 128, BN = 64, NA = 40;
    __shared__ float As[BM][BK];
    __shared__ float Ws[BK][BN];
    int tid = threadIdx.x;
    int tx = tid % 16;        // 4 cols
    int ty = tid / 16;        // 4 rows
    int rowBase = blockIdx.x * BM;

    float acc[4][4];
    #pragma unroll
    for (int i = 0; i < 4; i++)
        #pragma unroll
        for (int j = 0; j < 4; j++) acc[i][j] = 0.f;

    for (int kt = 0; kt < K; kt += BK) {
        #pragma unroll
        for (int t = 0; t < (BM * BK) / 256; t++) {
            int idx = tid + t * 256;
            int r = idx / BK, kk = idx % BK;
            int gr = rowBase + r;
            As[r][kk] = (gr < M) ? A[(size_t)gr * K + kt + kk] : 0.f;
        }
        #pragma unroll
        for (int t = 0; t < (BK * BN) / 256; t++) {
            int idx = tid + t * 256;
            int r = idx / BN, c = idx % BN;
            Ws[r][c] = (c < NA) ? W[(kt + r) * NA + c] : 0.f;
        }
        __syncthreads();
        #pragma unroll
        for (int kk = 0; kk < BK; kk++) {
            float b0 = Ws[kk][tx * 4 + 0];
            float b1 = Ws[kk][tx * 4 + 1];
            float b2 = Ws[kk][tx * 4 + 2];
            float b3 = Ws[kk][tx * 4 + 3];
            #pragma unroll
            for (int i = 0; i < 4; i++) {
                float a = As[ty * 4 + i][kk];
                acc[i][0] += a * b0;
                acc[i][1] += a * b1;
                acc[i][2] += a * b2;
                acc[i][3] += a * b3;
            }
        }
        __syncthreads();
    }
    #pragma unroll
    for (int i = 0; i < 4; i++) {
        int gr = rowBase + ty * 4 + i;
        if (gr >= M) continue;
        #pragma unroll
        for (int j = 0; j < 4; j++) {
            int c = tx * 4 + j;
            if (c < NA) C[(size_t)gr * NA + c] = acc[i][j];
        }
    }
}

// ---------------- aggregation, F=128 (one warp per node, 4-way MLP) --------
__global__ void agg128_k(const float* __restrict__ bias, int relu, int n) {
    int node = blockIdx.x * (blockDim.x >> 5) + (threadIdx.x >> 5);
    if (node >= n) return;
    int lane = threadIdx.x & 31;
    const float4* __restrict__ H4 = (const float4*)g_H;
    float* __restrict__ O = (float*)g_G;
    float di = g_dinv[node];
    float4 h = H4[(size_t)node * 32 + lane];
    float ax = di * h.x, ay = di * h.y, az = di * h.z, aw = di * h.w;  // self-loop
    int p = g_rowptr[node], pend = g_rowptr[node + 1];
    // 4-way unrolled gather for MLP
    for (; p + 4 <= pend; p += 4) {
        int s0 = g_col[p], s1 = g_col[p + 1], s2 = g_col[p + 2], s3 = g_col[p + 3];
        float d0 = g_dinv[s0], d1 = g_dinv[s1], d2 = g_dinv[s2], d3 = g_dinv[s3];
        float4 h0 = H4[(size_t)s0 * 32 + lane];
        float4 h1 = H4[(size_t)s1 * 32 + lane];
        float4 h2 = H4[(size_t)s2 * 32 + lane];
        float4 h3 = H4[(size_t)s3 * 32 + lane];
        ax += d0 * h0.x; ay += d0 * h0.y; az += d0 * h0.z; aw += d0 * h0.w;
        ax += d1 * h1.x; ay += d1 * h1.y; az += d1 * h1.z; aw += d1 * h1.w;
        ax += d2 * h2.x; ay += d2 * h2.y; az += d2 * h2.z; aw += d2 * h2.w;
        ax += d3 * h3.x; ay += d3 * h3.y; az += d3 * h3.z; aw += d3 * h3.w;
    }
    for (; p < pend; p++) {
        int s = g_col[p];
        float ds = g_dinv[s];
        float4 hs = H4[(size_t)s * 32 + lane];
        ax += ds * hs.x; ay += ds * hs.y; az += ds * hs.z; aw += ds * hs.w;
    }
    float4 bv = ((const float4*)bias)[lane];
    float ox = di * ax + bv.x, oy = di * ay + bv.y;
    float oz = di * az + bv.z, ow = di * aw + bv.w;
    if (relu) {
        ox = fmaxf(ox, 0.f); oy = fmaxf(oy, 0.f);
        oz = fmaxf(oz, 0.f); ow = fmaxf(ow, 0.f);
    }
    ((float4*)O)[(size_t)node * 32 + lane] = make_float4(ox, oy, oz, ow);
}

// ---------------- aggregation, F=40 (one warp per node) --------------------
__global__ void agg40_k(const float* __restrict__ bias, float* __restrict__ O, int n) {
    int node = blockIdx.x * (blockDim.x >> 5) + (threadIdx.x >> 5);
    if (node >= n) return;
    int lane = threadIdx.x & 31;
    const float* __restrict__ H = (const float*)g_H;
    bool hi = (lane < 8);
    float di = g_dinv[node];
    float a0 = di * H[(size_t)node * 40 + lane];
    float a1 = hi ? di * H[(size_t)node * 40 + 32 + lane] : 0.f;
    int p = g_rowptr[node], pend = g_rowptr[node + 1];
    for (; p + 2 <= pend; p += 2) {
        int s0 = g_col[p], s1 = g_col[p + 1];
        float d0 = g_dinv[s0], d1 = g_dinv[s1];
        float v0 = H[(size_t)s0 * 40 + lane];
        float v1 = H[(size_t)s1 * 40 + lane];
        a0 += d0 * v0 + d1 * v1;
        if (hi) {
            a1 += d0 * H[(size_t)s0 * 40 + 32 + lane];
            a1 += d1 * H[(size_t)s1 * 40 + 32 + lane];
        }
    }
    for (; p < pend; p++) {
        int s = g_col[p];
        float ds = g_dinv[s];
        a0 += ds * H[(size_t)s * 40 + lane];
        if (hi) a1 += ds * H[(size_t)s * 40 + 32 + lane];
    }
    O[(size_t)node * 40 + lane] = di * a0 + bias[lane];
    if (hi) O[(size_t)node * 40 + 32 + lane] = di * a1 + bias[32 + lane];
}

// ---------------- launch ----------------------------------------------------
// No CUDA runtime API calls here except kernel launches.
extern "C" void kernel_launch(void* const* d_in, const int* in_sizes, int n_in,
                              void* d_out, int out_size) {
    const float* x   = (const float*)d_in[0];
    const int*   ei  = (const int*)d_in[1];    // int32 (JAX x64 disabled)
    const float* W1  = (const float*)d_in[2];
    const float* b1  = (const float*)d_in[3];
    const float* Wm  = (const float*)d_in[4];
    const float* bm  = (const float*)d_in[5];
    const float* W2  = (const float*)d_in[6];
    const float* b2  = (const float*)d_in[7];
    float* out = (float*)d_out;

    const int n = NN, e = NE;
    const int* src = ei;        // edge_index[0, :]
    const int* dst = ei + e;    // edge_index[1, :]

    const int scanBlocks = (n + 1023) / 1024;   // 98

    // graph prep
    k_zero_deg<<<(n + 255) / 256, 256>>>(n);
    k_count<<<(e + 255) / 256, 256>>>(dst, e);
    k_scan_block<<<scanBlocks, 1024>>>(n);
    k_scan_sums<<<1, 32>>>(scanBlocks);
    k_finalize<<<scanBlocks, 1024>>>(n);
    k_scatter<<<(e + 255) / 256, 256>>>(src, dst, e);

    const int g128Blocks = (n + 127) / 128;     // 782
    const int aggBlocks  = (n + 7) / 8;         // warp per node, 8 warps/block

    // layer 1: g_H = x @ W1; g_G = relu(agg(g_H) + b1)
    gemm128_f2_k<0><<<g128Blocks, 256>>>(x, W1, n);
    agg128_k<<<aggBlocks, 256>>>(b1, 1, n);

    // layer 2: g_H = g_G @ Wm; g_G = relu(agg(g_H) + bm)
    gemm128_f2_k<1><<<g128Blocks, 256>>>(nullptr, Wm, n);
    agg128_k<<<aggBlocks, 256>>>(bm, 1, n);

    // layer 3: g_H[:, :40] = g_G @ W2; out = agg(g_H) + b2 (no relu)
    gemm40_k<<<(n + 63) / 64, 256>>>(W2, n);
    agg40_k<<<aggBlocks, 256>>>(b2, out, n);
}

// round 8
// speedup vs baseline: 1.2117x; 1.2117x over previous
#include <cuda_runtime.h>
#include <cuda_bf16.h>
#include <cstdint>

// Problem constants
#define NN 100000
#define NE 1600000

// ---------------- scratch (device globals) ----------------------------------
__device__ float g_H[(size_t)NN * 128];
__device__ float g_G[(size_t)NN * 128];
__device__ int   g_deg[NN];
__device__ int   g_rowptr[NN + 1];
__device__ int   g_cursor[NN];
__device__ int   g_col[NE];
__device__ float g_dinv[NN];
__device__ int   g_scantmp[NN];
__device__ int   g_bsums[128];
// W1 / Wm transposed + split into bf16 hi/lo, layout [n][k] (n-major)
__device__ __nv_bfloat16 g_Wth[2][128 * 128];
__device__ __nv_bfloat16 g_Wtl[2][128 * 128];

// ---------------- graph prep -----------------------------------------------
__global__ void k_zero_deg(int n) {
    int i = blockIdx.x * blockDim.x + threadIdx.x;
    if (i < n) g_deg[i] = 0;
}
__global__ void k_count(const int* __restrict__ dst, int e) {
    int i = blockIdx.x * blockDim.x + threadIdx.x;
    if (i < e) atomicAdd(&g_deg[dst[i]], 1);
}
__global__ void k_scan_block(int n) {
    int tid = threadIdx.x, lane = tid & 31, wid = tid >> 5;
    int i = blockIdx.x * 1024 + tid;
    int v = (i < n) ? g_deg[i] : 0;
    #pragma unroll
    for (int o = 1; o < 32; o <<= 1) {
        int t = __shfl_up_sync(0xffffffffu, v, o);
        if (lane >= o) v += t;
    }
    __shared__ int ws[32];
    if (lane == 31) ws[wid] = v;
    __syncthreads();
    if (wid == 0) {
        int w = ws[lane];
        #pragma unroll
        for (int o = 1; o < 32; o <<= 1) {
            int t = __shfl_up_sync(0xffffffffu, w, o);
            if (lane >= o) w += t;
        }
        ws[lane] = w;
    }
    __syncthreads();
    if (wid > 0) v += ws[wid - 1];
    if (i < n) g_scantmp[i] = v;
    if (tid == 1023) g_bsums[blockIdx.x] = v;
}
__global__ void k_scan_sums(int nb) {
    if (threadIdx.x == 0 && blockIdx.x == 0) {
        int acc = 0;
        for (int b = 0; b < nb; b++) {
            int t = g_bsums[b];
            g_bsums[b] = acc;
            acc += t;
        }
    }
}
__global__ void k_finalize(int n) {
    int i = blockIdx.x * 1024 + threadIdx.x;
    if (i >= n) return;
    int incl = g_scantmp[i] + g_bsums[blockIdx.x];
    int d = g_deg[i];
    int excl = incl - d;
    g_cursor[i] = excl;
    g_rowptr[i] = excl;
    if (i == n - 1) g_rowptr[n] = incl;
    g_dinv[i] = rsqrtf((float)(d + 1));
}
__global__ void k_scatter(const int* __restrict__ src,
                          const int* __restrict__ dst, int e) {
    int i = blockIdx.x * blockDim.x + threadIdx.x;
    if (i < e) {
        int d = dst[i];
        int p = atomicAdd(&g_cursor[d], 1);
        g_col[p] = src[i];
    }
}

// ---------------- W prep: W[k][n] f32 -> Wt[n][k] bf16 hi/lo ---------------
__global__ void k_wconv(const float* __restrict__ W, int slot) {
    int idx = blockIdx.x * blockDim.x + threadIdx.x;
    if (idx >= 128 * 128) return;
    int n = idx >> 7, k = idx & 127;
    float w = W[(size_t)k * 128 + n];
    __nv_bfloat16 h = __float2bfloat16_rn(w);
    __nv_bfloat16 l = __float2bfloat16_rn(w - __bfloat162float(h));
    g_Wth[slot][n * 128 + k] = h;
    g_Wtl[slot][n * 128 + k] = l;
}

// ---------------- mma helper -----------------------------------------------
__device__ __forceinline__ void mma_bf16(float* c, const uint32_t* a,
                                         const uint32_t* b) {
    asm volatile(
        "mma.sync.aligned.m16n8k16.row.col.f32.bf16.bf16.f32 "
        "{%0,%1,%2,%3}, {%4,%5,%6,%7}, {%8,%9}, {%0,%1,%2,%3};"
        : "+f"(c[0]), "+f"(c[1]), "+f"(c[2]), "+f"(c[3])
        : "r"(a[0]), "r"(a[1]), "r"(a[2]), "r"(a[3]), "r"(b[0]), "r"(b[1]));
}

// ---------------- split-bf16 tensor GEMM: C[M,128] = A[M,128] @ W[128,128] --
// BM=128, BN=128, K chunked by 32. 256 threads = 8 warps, warp tile 32x64.
// smem pad: rows of 40 bf16 (80 B) -> conflict-free b32 frag loads.
#define KP 40
template <int A_SEL>
__global__ void __launch_bounds__(256)
gemm128_mma_k(const float* __restrict__ Ap, int wslot, int M) {
    const float* __restrict__ A = (A_SEL == 0) ? Ap : (const float*)g_G;
    float* __restrict__ C = (float*)g_H;

    __shared__ __nv_bfloat16 Ash[128][KP];
    __shared__ __nv_bfloat16 Asl[128][KP];
    __shared__ __nv_bfloat16 Wsh[128][KP];
    __shared__ __nv_bfloat16 Wsl[128][KP];

    const int tid = threadIdx.x;
    const int wid = tid >> 5;
    const int lane = tid & 31;
    const int gid = lane >> 2;         // group id 0..7
    const int tig = lane & 3;          // thread in group
    const int mw = wid & 3;            // warp m-tile (32 rows)
    const int nw = wid >> 2;           // warp n-tile (64 cols)
    const int rowBase = blockIdx.x * 128;

    const int ar  = tid >> 1;          // A stage: row
    const int akl = (tid & 1) * 16;    // A stage: k-half
    const int wn  = tid >> 1;          // W stage: n row
    const int wkl = (tid & 1) * 16;    // W stage: k-half (16 elems)

    float acc[2][8][4];
    #pragma unroll
    for (int i = 0; i < 2; i++)
        #pragma unroll
        for (int j = 0; j < 8; j++)
            #pragma unroll
            for (int q = 0; q < 4; q++) acc[i][j][q] = 0.f;

    const __nv_bfloat16* __restrict__ Wth = g_Wth[wslot];
    const __nv_bfloat16* __restrict__ Wtl = g_Wtl[wslot];

    for (int kt = 0; kt < 128; kt += 32) {
        // ---- stage A chunk (convert f32 -> bf16 hi/lo), 16 elems/thread
        {
            const int gr = rowBase + ar;
            const bool valid = (gr < M);
            #pragma unroll
            for (int j = 0; j < 4; j++) {
                float4 v = valid
                    ? *(const float4*)&A[(size_t)gr * 128 + kt + akl + j * 4]
                    : make_float4(0.f, 0.f, 0.f, 0.f);
                float f[4] = {v.x, v.y, v.z, v.w};
                #pragma unroll
                for (int q = 0; q < 4; q++) {
                    __nv_bfloat16 h = __float2bfloat16_rn(f[q]);
                    __nv_bfloat16 l =
                        __float2bfloat16_rn(f[q] - __bfloat162float(h));
                    Ash[ar][akl + j * 4 + q] = h;
                    Asl[ar][akl + j * 4 + q] = l;
                }
            }
        }
        // ---- stage W chunk (bf16 [n][k]): 16 elems/thread = 2 x uint4
        {
            const size_t base = (size_t)wn * 128 + kt + wkl;
            uint4 vh0 = *(const uint4*)&Wth[base];
            uint4 vh1 = *(const uint4*)&Wth[base + 8];
            uint4 vl0 = *(const uint4*)&Wtl[base];
            uint4 vl1 = *(const uint4*)&Wtl[base + 8];
            *(uint4*)&Wsh[wn][wkl]     = vh0;
            *(uint4*)&Wsh[wn][wkl + 8] = vh1;
            *(uint4*)&Wsl[wn][wkl]     = vl0;
            *(uint4*)&Wsl[wn][wkl + 8] = vl1;
        }
        __syncthreads();

        #pragma unroll
        for (int ks = 0; ks < 32; ks += 16) {
            uint32_t Ah[2][4], Al[2][4], Bh[8][2], Bl[8][2];
            #pragma unroll
            for (int mt = 0; mt < 2; mt++) {
                const int r = mw * 32 + mt * 16 + gid;
                Ah[mt][0] = *(const uint32_t*)&Ash[r][ks + tig * 2];
                Ah[mt][1] = *(const uint32_t*)&Ash[r + 8][ks + tig * 2];
                Ah[mt][2] = *(const uint32_t*)&Ash[r][ks + 8 + tig * 2];
                Ah[mt][3] = *(const uint32_t*)&Ash[r + 8][ks + 8 + tig * 2];
                Al[mt][0] = *(const uint32_t*)&Asl[r][ks + tig * 2];
                Al[mt][1] = *(const uint32_t*)&Asl[r + 8][ks + tig * 2];
                Al[mt][2] = *(const uint32_t*)&Asl[r][ks + 8 + tig * 2];
                Al[mt][3] = *(const uint32_t*)&Asl[r + 8][ks + 8 + tig * 2];
            }
            #pragma unroll
            for (int nt = 0; nt < 8; nt++) {
                const int nn = nw * 64 + nt * 8 + gid;
                Bh[nt][0] = *(const uint32_t*)&Wsh[nn][ks + tig * 2];
                Bh[nt][1] = *(const uint32_t*)&Wsh[nn][ks + 8 + tig * 2];
                Bl[nt][0] = *(const uint32_t*)&Wsl[nn][ks + tig * 2];
                Bl[nt][1] = *(const uint32_t*)&Wsl[nn][ks + 8 + tig * 2];
            }
            #pragma unroll
            for (int mt = 0; mt < 2; mt++)
                #pragma unroll
                for (int nt = 0; nt < 8; nt++)
                    mma_bf16(acc[mt][nt], Ah[mt], Bh[nt]);
            #pragma unroll
            for (int mt = 0; mt < 2; mt++)
                #pragma unroll
                for (int nt = 0; nt < 8; nt++)
                    mma_bf16(acc[mt][nt], Ah[mt], Bl[nt]);
            #pragma unroll
            for (int mt = 0; mt < 2; mt++)
                #pragma unroll
                for (int nt = 0; nt < 8; nt++)
                    mma_bf16(acc[mt][nt], Al[mt], Bh[nt]);
        }
        __syncthreads();
    }

    // ---- epilogue
    #pragma unroll
    for (int mt = 0; mt < 2; mt++) {
        const int r = rowBase + mw * 32 + mt * 16 + gid;
        #pragma unroll
        for (int nt = 0; nt < 8; nt++) {
            const int col = nw * 64 + nt * 8 + tig * 2;
            if (r < M)
                *(float2*)&C[(size_t)r * 128 + col] =
                    make_float2(acc[mt][nt][0], acc[mt][nt][1]);
            if (r + 8 < M)
                *(float2*)&C[(size_t)(r + 8) * 128 + col] =
                    make_float2(acc[mt][nt][2], acc[mt][nt][3]);
        }
    }
}

// ---------------- small GEMM for layer 3: C[M,40] = A[M,128] @ W[128,40] ----
__global__ void gemm40_k(const float* __restrict__ W, int M) {
    const float* __restrict__ A = (const float*)g_G;
    float* __restrict__ C = (float*)g_H;
    constexpr int BM = 64, BK = 32, K = 128, BN = 64, NA = 40;
    __shared__ float As[BM][BK];
    __shared__ float Ws[BK][BN];
    int tid = threadIdx.x;
    int tx = tid % 16;
    int ty = tid / 16;
    int rowBase = blockIdx.x * BM;

    float acc[4][4];
    #pragma unroll
    for (int i = 0; i < 4; i++)
        #pragma unroll
        for (int j = 0; j < 4; j++) acc[i][j] = 0.f;

    for (int kt = 0; kt < K; kt += BK) {
        #pragma unroll
        for (int t = 0; t < (BM * BK) / 256; t++) {
            int idx = tid + t * 256;
            int r = idx / BK, kk = idx % BK;
            int gr = rowBase + r;
            As[r][kk] = (gr < M) ? A[(size_t)gr * K + kt + kk] : 0.f;
        }
        #pragma unroll
        for (int t = 0; t < (BK * BN) / 256; t++) {
            int idx = tid + t * 256;
            int r = idx / BN, c = idx % BN;
            Ws[r][c] = (c < NA) ? W[(kt + r) * NA + c] : 0.f;
        }
        __syncthreads();
        #pragma unroll
        for (int kk = 0; kk < BK; kk++) {
            float b0 = Ws[kk][tx * 4 + 0];
            float b1 = Ws[kk][tx * 4 + 1];
            float b2 = Ws[kk][tx * 4 + 2];
            float b3 = Ws[kk][tx * 4 + 3];
            #pragma unroll
            for (int i = 0; i < 4; i++) {
                float a = As[ty * 4 + i][kk];
                acc[i][0] += a * b0;
                acc[i][1] += a * b1;
                acc[i][2] += a * b2;
                acc[i][3] += a * b3;
            }
        }
        __syncthreads();
    }
    #pragma unroll
    for (int i = 0; i < 4; i++) {
        int gr = rowBase + ty * 4 + i;
        if (gr >= M) continue;
        #pragma unroll
        for (int j = 0; j < 4; j++) {
            int c = tx * 4 + j;
            if (c < NA) C[(size_t)gr * NA + c] = acc[i][j];
        }
    }
}

// ---------------- aggregation, F=128 (one warp per node, 4-way MLP) --------
__global__ void agg128_k(const float* __restrict__ bias, int relu, int n) {
    int node = blockIdx.x * (blockDim.x >> 5) + (threadIdx.x >> 5);
    if (node >= n) return;
    int lane = threadIdx.x & 31;
    const float4* __restrict__ H4 = (const float4*)g_H;
    float* __restrict__ O = (float*)g_G;
    float di = g_dinv[node];
    float4 h = H4[(size_t)node * 32 + lane];
    float ax = di * h.x, ay = di * h.y, az = di * h.z, aw = di * h.w;
    int p = g_rowptr[node], pend = g_rowptr[node + 1];
    for (; p + 4 <= pend; p += 4) {
        int s0 = g_col[p], s1 = g_col[p + 1], s2 = g_col[p + 2], s3 = g_col[p + 3];
        float d0 = g_dinv[s0], d1 = g_dinv[s1], d2 = g_dinv[s2], d3 = g_dinv[s3];
        float4 h0 = H4[(size_t)s0 * 32 + lane];
        float4 h1 = H4[(size_t)s1 * 32 + lane];
        float4 h2 = H4[(size_t)s2 * 32 + lane];
        float4 h3 = H4[(size_t)s3 * 32 + lane];
        ax += d0 * h0.x; ay += d0 * h0.y; az += d0 * h0.z; aw += d0 * h0.w;
        ax += d1 * h1.x; ay += d1 * h1.y; az += d1 * h1.z; aw += d1 * h1.w;
        ax += d2 * h2.x; ay += d2 * h2.y; az += d2 * h2.z; aw += d2 * h2.w;
        ax += d3 * h3.x; ay += d3 * h3.y; az += d3 * h3.z; aw += d3 * h3.w;
    }
    for (; p < pend; p++) {
        int s = g_col[p];
        float ds = g_dinv[s];
        float4 hs = H4[(size_t)s * 32 + lane];
        ax += ds * hs.x; ay += ds * hs.y; az += ds * hs.z; aw += ds * hs.w;
    }
    float4 bv = ((const float4*)bias)[lane];
    float ox = di * ax + bv.x, oy = di * ay + bv.y;
    float oz = di * az + bv.z, ow = di * aw + bv.w;
    if (relu) {
        ox = fmaxf(ox, 0.f); oy = fmaxf(oy, 0.f);
        oz = fmaxf(oz, 0.f); ow = fmaxf(ow, 0.f);
    }
    ((float4*)O)[(size_t)node * 32 + lane] = make_float4(ox, oy, oz, ow);
}

// ---------------- aggregation, F=40 ----------------------------------------
__global__ void agg40_k(const float* __restrict__ bias, float* __restrict__ O, int n) {
    int node = blockIdx.x * (blockDim.x >> 5) + (threadIdx.x >> 5);
    if (node >= n) return;
    int lane = threadIdx.x & 31;
    const float* __restrict__ H = (const float*)g_H;
    bool hi = (lane < 8);
    float di = g_dinv[node];
    float a0 = di * H[(size_t)node * 40 + lane];
    float a1 = hi ? di * H[(size_t)node * 40 + 32 + lane] : 0.f;
    int p = g_rowptr[node], pend = g_rowptr[node + 1];
    for (; p + 2 <= pend; p += 2) {
        int s0 = g_col[p], s1 = g_col[p + 1];
        float d0 = g_dinv[s0], d1 = g_dinv[s1];
        a0 += d0 * H[(size_t)s0 * 40 + lane] + d1 * H[(size_t)s1 * 40 + lane];
        if (hi) {
            a1 += d0 * H[(size_t)s0 * 40 + 32 + lane];
            a1 += d1 * H[(size_t)s1 * 40 + 32 + lane];
        }
    }
    for (; p < pend; p++) {
        int s = g_col[p];
        float ds = g_dinv[s];
        a0 += ds * H[(size_t)s * 40 + lane];
        if (hi) a1 += ds * H[(size_t)s * 40 + 32 + lane];
    }
    O[(size_t)node * 40 + lane] = di * a0 + bias[lane];
    if (hi) O[(size_t)node * 40 + 32 + lane] = di * a1 + bias[32 + lane];
}

// ---------------- launch ----------------------------------------------------
extern "C" void kernel_launch(void* const* d_in, const int* in_sizes, int n_in,
                              void* d_out, int out_size) {
    const float* x   = (const float*)d_in[0];
    const int*   ei  = (const int*)d_in[1];    // int32 (JAX x64 disabled)
    const float* W1  = (const float*)d_in[2];
    const float* b1  = (const float*)d_in[3];
    const float* Wm  = (const float*)d_in[4];
    const float* bm  = (const float*)d_in[5];
    const float* W2  = (const float*)d_in[6];
    const float* b2  = (const float*)d_in[7];
    float* out = (float*)d_out;

    const int n = NN, e = NE;
    const int* src = ei;
    const int* dst = ei + e;

    const int scanBlocks = (n + 1023) / 1024;

    // graph prep + weight conversion
    k_zero_deg<<<(n + 255) / 256, 256>>>(n);
    k_count<<<(e + 255) / 256, 256>>>(dst, e);
    k_scan_block<<<scanBlocks, 1024>>>(n);
    k_scan_sums<<<1, 32>>>(scanBlocks);
    k_finalize<<<scanBlocks, 1024>>>(n);
    k_scatter<<<(e + 255) / 256, 256>>>(src, dst, e);
    k_wconv<<<64, 256>>>(W1, 0);
    k_wconv<<<64, 256>>>(Wm, 1);

    const int tcBlocks  = (n + 127) / 128;      // 782
    const int aggBlocks = (n + 7) / 8;

    // layer 1: g_H = x @ W1 (mma); g_G = relu(agg(g_H) + b1)
    gemm128_mma_k<0><<<tcBlocks, 256>>>(x, 0, n);
    agg128_k<<<aggBlocks, 256>>>(b1, 1, n);

    // layer 2
    gemm128_mma_k<1><<<tcBlocks, 256>>>(nullptr, 1, n);
    agg128_k<<<aggBlocks, 256>>>(bm, 1, n);

    // layer 3
    gemm40_k<<<(n + 63) / 64, 256>>>(W2, n);
    agg40_k<<<aggBlocks, 256>>>(b2, out, n);
}